// round 5
// baseline (speedup 1.0000x reference)
#include <cuda_runtime.h>
#include <cstdint>

#define DIM_NODE 64
#define DIM_EDGE 32
#define D_IN1    160
#define OUT_DIM  64
#define MAX_NODES 50000
#define E_TILE   128
#define NEG_SLOPE 0.01f

// Per-node precomputed partials: P[n][0:128] = x[n]@W1a^T, P[n][128:256] = x[n]@W1b^T
__device__ float g_P[(size_t)MAX_NODES * 256];

__device__ __forceinline__ float to_tf32(float x) {
    uint32_t u; asm("cvt.rna.tf32.f32 %0, %1;" : "=r"(u) : "f"(x));
    return __uint_as_float(u);
}
__device__ __forceinline__ uint32_t tf32_bits(float x) {
    uint32_t u; asm("cvt.rna.tf32.f32 %0, %1;" : "=r"(u) : "f"(x));
    return u;
}
__device__ __forceinline__ void mma_tf32(float* d, const uint32_t* a, const uint32_t* b) {
    asm volatile(
        "mma.sync.aligned.m16n8k8.row.col.f32.tf32.tf32.f32 "
        "{%0,%1,%2,%3}, {%4,%5,%6,%7}, {%8,%9}, {%0,%1,%2,%3};"
        : "+f"(d[0]), "+f"(d[1]), "+f"(d[2]), "+f"(d[3])
        : "r"(a[0]), "r"(a[1]), "r"(a[2]), "r"(a[3]), "r"(b[0]), "r"(b[1]));
}
__device__ __forceinline__ uint32_t smem_u32(const void* p) {
    uint32_t a;
    asm("{ .reg .u64 t; cvta.to.shared.u64 t, %1; cvt.u32.u64 %0, t; }" : "=r"(a) : "l"(p));
    return a;
}
__device__ __forceinline__ void cp_async16(uint32_t dst, const void* src, uint32_t srcsize) {
    asm volatile("cp.async.cg.shared.global [%0], [%1], 16, %2;"
                 :: "r"(dst), "l"(src), "r"(srcsize));
}
__device__ __forceinline__ void cp_async_commit() {
    asm volatile("cp.async.commit_group;" ::: "memory");
}
__device__ __forceinline__ void cp_async_wait0() {
    asm volatile("cp.async.wait_group 0;" ::: "memory");
}

// ---------------------------------------------------------------------------
// SMEM layout (float offsets):
//   EA    [128][36]  @0      (per tile, raw f32 via cp.async)
//   PANEL [128][68]  @4608   (C1/h half-panel, K=64 at a time)
//   W1C   [128][36]  @13312  (persistent, tf32)
//   W2    [64][132]  @17920  (persistent, tf32)
//   b1 @26368, b2 @26496, src @26560, dst @26688
// ---------------------------------------------------------------------------
#define EA_F    0
#define PANEL_F 4608
#define W1C_F   13312
#define W2_F    17920
#define B1_F    26368
#define B2_F    26496
#define SRC_F   26560
#define DST_F   26688
#define SMEM_EDGE_FLOATS 26816          // 107264 bytes

// ---------------------------------------------------------------------------
// Kernel 1: node precompute.  64 nodes/block, 256 threads, 8x8 microtile.
// ---------------------------------------------------------------------------
__global__ __launch_bounds__(256, 2) void k_precompute(
    const float* __restrict__ x, const float* __restrict__ W1, int n_nodes)
{
    extern __shared__ float sm[];
    float* s_w = sm;               // [64][257]
    float* s_x = sm + 64 * 257;    // [64][68]
    const int t = threadIdx.x;

    #pragma unroll
    for (int i = 0; i < 64; ++i) {
        int idx = i * 256 + t;
        int c = idx >> 6, d = idx & 63;
        float v = (c < 128) ? W1[c * D_IN1 + d] : W1[(c - 128) * D_IN1 + 64 + d];
        s_w[d * 257 + c] = v;
    }
    const int node0 = blockIdx.x * 64;
    #pragma unroll
    for (int i = 0; i < 16; ++i) {
        int idx = i * 256 + t;
        int n = idx >> 6, d = idx & 63;
        int gn = node0 + n;
        s_x[n * 68 + d] = (gn < n_nodes) ? x[(size_t)gn * DIM_NODE + d] : 0.f;
    }
    __syncthreads();

    const int n0 = t & 7;
    const int c0 = (t >> 3) * 8;
    float acc[8][8];
    #pragma unroll
    for (int i = 0; i < 8; ++i)
        #pragma unroll
        for (int j = 0; j < 8; ++j) acc[i][j] = 0.f;

    #pragma unroll 4
    for (int d = 0; d < 64; ++d) {
        float xa[8], wb[8];
        #pragma unroll
        for (int i = 0; i < 8; ++i) xa[i] = s_x[(n0 + 8 * i) * 68 + d];
        #pragma unroll
        for (int j = 0; j < 8; ++j) wb[j] = s_w[d * 257 + c0 + j];
        #pragma unroll
        for (int i = 0; i < 8; ++i)
            #pragma unroll
            for (int j = 0; j < 8; ++j)
                acc[i][j] = fmaf(xa[i], wb[j], acc[i][j]);
    }
    #pragma unroll
    for (int i = 0; i < 8; ++i) {
        int gn = node0 + n0 + 8 * i;
        if (gn < n_nodes) {
            float4* p = (float4*)(g_P + (size_t)gn * 256 + c0);
            p[0] = make_float4(acc[i][0], acc[i][1], acc[i][2], acc[i][3]);
            p[1] = make_float4(acc[i][4], acc[i][5], acc[i][6], acc[i][7]);
        }
    }
}

// ---------------------------------------------------------------------------
// Kernel 2: persistent mma.sync tf32 edge MLP, half-K panels.
// ---------------------------------------------------------------------------
__global__ __launch_bounds__(256, 2) void k_edge(
    const int*   __restrict__ eidx,
    const float* __restrict__ ea,
    const float* __restrict__ W1,
    const float* __restrict__ b1,
    const float* __restrict__ W2g,
    const float* __restrict__ b2,
    float*       __restrict__ out,
    int E, int n_tiles)
{
    extern __shared__ float sm[];
    const uint32_t sb = smem_u32(sm);
    const int t   = threadIdx.x;
    const int wid = t >> 5;
    const int lid = t & 31;
    const int qr  = lid >> 2;      // 0..7
    const int ql  = lid & 3;       // 0..3
    const int wm  = wid & 3;       // warp M coord (rows of 32)
    const int wn  = wid >> 2;      // warp N coord
    const int hl  = lid >> 4;      // phase-B half-lane (0/1)
    const int cf  = (lid & 15) * 4;

    int* s_src = (int*)(sm + SRC_F);
    int* s_dst = (int*)(sm + DST_F);

    // ======== CTA prologue: persistent weights (once) ========
    // W1c: [128 n][36] tf32 (cols 128..159 of W1)
    #pragma unroll
    for (int i = 0; i < 4; ++i) {
        int idx = i * 256 + t;                // float4 id, 0..1023
        int n = idx >> 3, kc = idx & 7;
        float4 v = *(const float4*)(W1 + n * D_IN1 + 128 + kc * 4);
        v.x = to_tf32(v.x); v.y = to_tf32(v.y); v.z = to_tf32(v.z); v.w = to_tf32(v.w);
        *(float4*)(sm + W1C_F + n * 36 + kc * 4) = v;
    }
    // W2: [64 n][132] tf32
    #pragma unroll
    for (int i = 0; i < 8; ++i) {
        int idx = i * 256 + t;                // 0..2047 float4s
        int n = idx >> 5, kc = idx & 31;
        float4 v = ((const float4*)W2g)[n * 32 + kc];
        v.x = to_tf32(v.x); v.y = to_tf32(v.y); v.z = to_tf32(v.z); v.w = to_tf32(v.w);
        *(float4*)(sm + W2_F + n * 132 + kc * 4) = v;
    }
    if (t < 128)      sm[B1_F + t] = b1[t];
    else if (t < 192) sm[B2_F + t - 128] = b2[t - 128];
    __syncthreads();

    // Bias fragments in registers
    float2 bb2[4];
    #pragma unroll
    for (int j = 0; j < 4; ++j)
        bb2[j] = *(const float2*)(sm + B2_F + wn * 32 + j * 8 + 2 * ql);
    float4 bb1h[2];
    #pragma unroll
    for (int hn = 0; hn < 2; ++hn)
        bb1h[hn] = *(const float4*)(sm + B1_F + hn * 64 + cf);

    const uint32_t* u_ea  = (const uint32_t*)(sm + EA_F);
    const float*    f_ea  = (const float*)(sm + EA_F);
    const uint32_t* u_w1c = (const uint32_t*)(sm + W1C_F);
    const uint32_t* u_w2  = (const uint32_t*)(sm + W2_F);
    const uint32_t* u_pan = (const uint32_t*)(sm + PANEL_F);

    // ======== persistent tile loop ========
    for (int tile = blockIdx.x; tile < n_tiles; tile += gridDim.x) {
        const int ebase = tile * E_TILE;

        // ---- stage ea via cp.async (raw f32), indices via regular ld ----
        #pragma unroll
        for (int i = 0; i < 4; ++i) {
            int idx = i * 256 + t;            // float4 id, 0..1023
            int m = idx >> 3, kc = idx & 7;
            int ge = ebase + m;
            uint32_t dst = sb + (EA_F + m * 36 + kc * 4) * 4;
            cp_async16(dst, ea + (size_t)ge * DIM_EDGE + kc * 4, (ge < E) ? 16u : 0u);
        }
        cp_async_commit();
        if (t < 128) {
            int e = ebase + t;
            s_src[t] = (e < E) ? eidx[e] : 0;
        } else {
            int e = ebase + (t - 128);
            s_dst[t - 128] = (e < E) ? eidx[E + e] : 0;
        }
        cp_async_wait0();
        __syncthreads();                       // (A)

        float acc2[2][4][4];
        #pragma unroll
        for (int i = 0; i < 2; ++i)
            #pragma unroll
            for (int j = 0; j < 4; ++j)
                #pragma unroll
                for (int c = 0; c < 4; ++c) acc2[i][j][c] = 0.f;

        #pragma unroll
        for (int hn = 0; hn < 2; ++hn) {
            if (hn) __syncthreads();           // panel drained by GEMM2 h0

            // ---- GEMM1 half: C1[:, hn*64 .. +64) (M=32, N=32 per warp) ----
            float acc1[2][4][4];
            #pragma unroll
            for (int i = 0; i < 2; ++i)
                #pragma unroll
                for (int j = 0; j < 4; ++j)
                    #pragma unroll
                    for (int c = 0; c < 4; ++c) acc1[i][j][c] = 0.f;

            #pragma unroll
            for (int kt = 0; kt < 4; ++kt) {
                const int k = kt * 8 + ql;
                uint32_t a[2][4];
                #pragma unroll
                for (int i = 0; i < 2; ++i) {
                    int r = wm * 32 + i * 16 + qr;
                    a[i][0] = tf32_bits(f_ea[r * 36 + k]);
                    a[i][1] = tf32_bits(f_ea[(r + 8) * 36 + k]);
                    a[i][2] = tf32_bits(f_ea[r * 36 + k + 4]);
                    a[i][3] = tf32_bits(f_ea[(r + 8) * 36 + k + 4]);
                }
                uint32_t b[4][2];
                #pragma unroll
                for (int j = 0; j < 4; ++j) {
                    int n = hn * 64 + wn * 32 + j * 8 + qr;
                    b[j][0] = u_w1c[n * 36 + k];
                    b[j][1] = u_w1c[n * 36 + k + 4];
                }
                #pragma unroll
                for (int i = 0; i < 2; ++i)
                    #pragma unroll
                    for (int j = 0; j < 4; ++j)
                        mma_tf32(acc1[i][j], a[i], b[j]);
            }

            // ---- STS C1 half -> panel [128][68], local cols 0..63 ----
            #pragma unroll
            for (int i = 0; i < 2; ++i) {
                int r = wm * 32 + i * 16 + qr;
                #pragma unroll
                for (int j = 0; j < 4; ++j) {
                    int c = wn * 32 + j * 8 + 2 * ql;
                    *(float2*)(sm + PANEL_F + r * 68 + c)       = make_float2(acc1[i][j][0], acc1[i][j][1]);
                    *(float2*)(sm + PANEL_F + (r + 8) * 68 + c) = make_float2(acc1[i][j][2], acc1[i][j][3]);
                }
            }
            __syncthreads();                   // (B/E)

            // ---- Phase B half: h = tf32(leaky(C1 + P_src + P_dst + b1)) ----
            {
                const int m0 = wid * 16 + hl;  // rows m0 + 2g
                #pragma unroll
                for (int gb = 0; gb < 2; ++gb) {
                    float4 vs[4], vd[4], hh[4];
                    #pragma unroll
                    for (int g = 0; g < 4; ++g) {
                        int m = m0 + (gb * 4 + g) * 2;
                        vs[g] = *(const float4*)(g_P + (size_t)s_src[m] * 256 + hn * 64 + cf);
                        vd[g] = *(const float4*)(g_P + (size_t)s_dst[m] * 256 + 128 + hn * 64 + cf);
                    }
                    #pragma unroll
                    for (int g = 0; g < 4; ++g)
                        hh[g] = *(const float4*)(sm + PANEL_F + (m0 + (gb * 4 + g) * 2) * 68 + cf);
                    #pragma unroll
                    for (int g = 0; g < 4; ++g) {
                        float h0 = hh[g].x + vs[g].x + vd[g].x + bb1h[hn].x;
                        float h1 = hh[g].y + vs[g].y + vd[g].y + bb1h[hn].y;
                        float h2 = hh[g].z + vs[g].z + vd[g].z + bb1h[hn].z;
                        float h3 = hh[g].w + vs[g].w + vd[g].w + bb1h[hn].w;
                        h0 = (h0 >= 0.f) ? h0 : NEG_SLOPE * h0;
                        h1 = (h1 >= 0.f) ? h1 : NEG_SLOPE * h1;
                        h2 = (h2 >= 0.f) ? h2 : NEG_SLOPE * h2;
                        h3 = (h3 >= 0.f) ? h3 : NEG_SLOPE * h3;
                        *(float4*)(sm + PANEL_F + (m0 + (gb * 4 + g) * 2) * 68 + cf) =
                            make_float4(to_tf32(h0), to_tf32(h1), to_tf32(h2), to_tf32(h3));
                    }
                }
            }
            __syncthreads();                   // (C/F)

            // ---- GEMM2 half: accumulate K = hn*64 .. +64 ----
            #pragma unroll
            for (int kt = 0; kt < 8; ++kt) {
                const int k  = kt * 8 + ql;            // panel-local k
                const int kg = hn * 64 + k;            // global k for W2
                uint32_t a[2][4];
                #pragma unroll
                for (int i = 0; i < 2; ++i) {
                    int r = wm * 32 + i * 16 + qr;
                    a[i][0] = u_pan[r * 68 + k];
                    a[i][1] = u_pan[(r + 8) * 68 + k];
                    a[i][2] = u_pan[r * 68 + k + 4];
                    a[i][3] = u_pan[(r + 8) * 68 + k + 4];
                }
                uint32_t b[4][2];
                #pragma unroll
                for (int j = 0; j < 4; ++j) {
                    int n = wn * 32 + j * 8 + qr;
                    b[j][0] = u_w2[n * 132 + kg];
                    b[j][1] = u_w2[n * 132 + kg + 4];
                }
                #pragma unroll
                for (int i = 0; i < 2; ++i)
                    #pragma unroll
                    for (int j = 0; j < 4; ++j)
                        mma_tf32(acc2[i][j], a[i], b[j]);
            }
        }

        // ---- Epilogue: direct STG from C2 fragments (+b2) ----
        #pragma unroll
        for (int i = 0; i < 2; ++i) {
            int r = wm * 32 + i * 16 + qr;
            int ge0 = ebase + r;
            int ge1 = ge0 + 8;
            #pragma unroll
            for (int j = 0; j < 4; ++j) {
                int c = wn * 32 + j * 8 + 2 * ql;
                if (ge0 < E)
                    *(float2*)(out + (size_t)ge0 * OUT_DIM + c) =
                        make_float2(acc2[i][j][0] + bb2[j].x, acc2[i][j][1] + bb2[j].y);
                if (ge1 < E)
                    *(float2*)(out + (size_t)ge1 * OUT_DIM + c) =
                        make_float2(acc2[i][j][2] + bb2[j].x, acc2[i][j][3] + bb2[j].y);
            }
        }
        // no barrier needed: next tile's stage writes only EA/src/dst, and the
        // (A) barrier after staging orders them against this tile's readers.
    }
}

// ---------------------------------------------------------------------------
extern "C" void kernel_launch(void* const* d_in, const int* in_sizes, int n_in,
                              void* d_out, int out_size)
{
    const float* x    = (const float*)d_in[0];
    const int*   eidx = (const int*)  d_in[1];
    const float* ea   = (const float*)d_in[2];
    const float* W1   = (const float*)d_in[3];
    const float* b1   = (const float*)d_in[4];
    const float* W2   = (const float*)d_in[5];
    const float* b2   = (const float*)d_in[6];
    float* out = (float*)d_out;

    int n_nodes = in_sizes[0] / DIM_NODE;
    if (n_nodes > MAX_NODES) n_nodes = MAX_NODES;
    int E = in_sizes[2] / DIM_EDGE;
    int n_tiles = (E + E_TILE - 1) / E_TILE;

    const int smem1 = (64 * 257 + 64 * 68) * 4;       // 83200 B
    const int smem2 = SMEM_EDGE_FLOATS * 4;           // 107264 B

    cudaFuncSetAttribute(k_precompute, cudaFuncAttributeMaxDynamicSharedMemorySize, smem1);
    cudaFuncSetAttribute(k_edge,       cudaFuncAttributeMaxDynamicSharedMemorySize, smem2);

    int n_blocks = 148 * 8;
    if (n_blocks > n_tiles) n_blocks = n_tiles;

    k_precompute<<<(n_nodes + 63) / 64, 256, smem1>>>(x, W1, n_nodes);
    k_edge<<<n_blocks, 256, smem2>>>(eidx, ea, W1, b1, W2, b2, out, E, n_tiles);
}